// round 12
// baseline (speedup 1.0000x reference)
#include <cuda_runtime.h>
#include <math.h>

#define B_   8
#define T_   2048
#define E_   256
#define H_   8
#define DH_  32
#define M_   (B_ * T_)    // 16384 rows
#define N3_  (3 * E_)     // 768

// Scratch (allocation-free rule: __device__ globals)
__device__ float g_qkv[(size_t)M_ * N3_];   // [16384, 768]  q|k|v per row
__device__ float g_att[(size_t)M_ * E_];    // [16384, 256]  attention output (b,t,h,d)

// ---------------------------------------------------------------------------
// GEMM + bias: C[M,N] = A[M,K] @ W[K,N] + bias[N]
// Tile 64x64, BK=16, 256 threads, 4x4 microtile per thread.
// M,N,K all multiples of 64/16 for this problem -> no bounds checks.
// ---------------------------------------------------------------------------
__global__ void __launch_bounds__(256) sgemm_bias_kernel(
    const float* __restrict__ A, const float* __restrict__ W,
    const float* __restrict__ bias, float* __restrict__ C,
    int M, int N, int K)
{
    __shared__ float As[16][68];   // [k][m]
    __shared__ float Bs[16][68];   // [k][n]

    const int bm = blockIdx.y * 64;
    const int bn = blockIdx.x * 64;
    const int tid = threadIdx.x;
    const int tx = tid & 15;       // column group
    const int ty = tid >> 4;       // row group

    float acc[4][4] = {};

    for (int k0 = 0; k0 < K; k0 += 16) {
        #pragma unroll
        for (int i = 0; i < 4; i++) {
            int idx = tid + i * 256;
            int r = idx >> 4, c = idx & 15;          // 64 rows x 16 cols
            As[c][r] = A[(size_t)(bm + r) * K + (k0 + c)];
        }
        #pragma unroll
        for (int i = 0; i < 4; i++) {
            int idx = tid + i * 256;
            int r = idx >> 6, c = idx & 63;          // 16 rows x 64 cols
            Bs[r][c] = W[(size_t)(k0 + r) * N + (bn + c)];
        }
        __syncthreads();

        #pragma unroll
        for (int kk = 0; kk < 16; kk++) {
            float a[4], bv[4];
            #pragma unroll
            for (int i = 0; i < 4; i++) a[i]  = As[kk][ty * 4 + i];
            #pragma unroll
            for (int j = 0; j < 4; j++) bv[j] = Bs[kk][tx * 4 + j];
            #pragma unroll
            for (int i = 0; i < 4; i++)
                #pragma unroll
                for (int j = 0; j < 4; j++)
                    acc[i][j] = fmaf(a[i], bv[j], acc[i][j]);
        }
        __syncthreads();
    }

    #pragma unroll
    for (int i = 0; i < 4; i++) {
        int row = bm + ty * 4 + i;
        int col = bn + tx * 4;
        float4 r;
        r.x = acc[i][0] + bias[col + 0];
        r.y = acc[i][1] + bias[col + 1];
        r.z = acc[i][2] + bias[col + 2];
        r.w = acc[i][3] + bias[col + 3];
        *reinterpret_cast<float4*>(&C[(size_t)row * N + col]) = r;
    }
}

// ---------------------------------------------------------------------------
// RoPE in-place on q (cols [0,256)) and k (cols [256,512)) of g_qkv.
// One thread per (row, q/k, head, pair). freq_i = 10000^(-i/16), i in [0,16).
// angles up to 2047 rad -> use accurate sincosf (range reduction).
// ---------------------------------------------------------------------------
__global__ void __launch_bounds__(256) rope_kernel(float* __restrict__ qkv)
{
    const int total = M_ * 2 * H_ * (DH_ / 2);   // 4,194,304
    int idx = blockIdx.x * blockDim.x + threadIdx.x;
    if (idx >= total) return;

    int i = idx & 15;            // pair index
    int h = (idx >> 4) & 7;      // head
    int s = (idx >> 7) & 1;      // 0 = q, 1 = k
    int n = idx >> 8;            // row (b*T + t)
    int t = n & (T_ - 1);        // sequence position

    // 10000^(-i/16) = 2^(-i/16 * log2(10000))
    float freq = exp2f(-(float)i * (13.287712379549449f / 16.0f));
    float ang = (float)t * freq;
    float sn, cs;
    sincosf(ang, &sn, &cs);

    size_t base = (size_t)n * N3_ + s * E_ + h * DH_ + 2 * i;
    float x0 = qkv[base];
    float x1 = qkv[base + 1];
    qkv[base]     = x0 * cs - x1 * sn;
    qkv[base + 1] = x1 * cs + x0 * sn;
}

// ---------------------------------------------------------------------------
// Causal flash attention, fp32, Dh=32.
// Grid: (T/64, B*H). 256 threads: tx=tid&15 (cols), ty=tid>>4 (rows).
// Each thread: 4x4 of the 64x64 score tile; O fragment = 4 rows x 2 dims.
// Row softmax groups (fixed ty, 16 lanes) are contiguous within a warp ->
// shuffle reductions + __syncwarp between P-store and PV.
// Output layout: att[(b*T+t)*256 + h*32 + d]  (== bthd reshape).
// ---------------------------------------------------------------------------
__global__ void __launch_bounds__(256) flash_attn_kernel(
    const float* __restrict__ qkv, float* __restrict__ att)
{
    const int qtile = blockIdx.x;         // 0..31
    const int bh    = blockIdx.y;         // 0..63
    const int b = bh >> 3, h = bh & 7;
    const int tid = threadIdx.x;
    const int tx = tid & 15, ty = tid >> 4;

    __shared__ float Qs[64][32];
    __shared__ float Ks[64][33];
    __shared__ float Vs[64][32];
    __shared__ float Ps[64][68];

    const size_t row_base = (size_t)(b * T_) * N3_;
    const int qcol = h * DH_;
    const int kcol = E_ + h * DH_;
    const int vcol = 2 * E_ + h * DH_;

    // Load Q tile (coalesced: 32 floats per row = one 128B line)
    #pragma unroll
    for (int i = 0; i < 8; i++) {
        int idx = tid + i * 256;
        int r = idx >> 5, d = idx & 31;
        Qs[r][d] = qkv[row_base + (size_t)(qtile * 64 + r) * N3_ + qcol + d];
    }

    float m_i[4], l_i[4], o[4][2];
    #pragma unroll
    for (int i = 0; i < 4; i++) {
        m_i[i] = -1e30f; l_i[i] = 0.f; o[i][0] = 0.f; o[i][1] = 0.f;
    }

    const float scale = 0.17677669529663687f;  // 1/sqrt(32)

    for (int kt = 0; kt <= qtile; kt++) {
        __syncthreads();   // Vs/Ks free to overwrite (also covers Q-load on iter 0)
        #pragma unroll
        for (int i = 0; i < 8; i++) {
            int idx = tid + i * 256;
            int r = idx >> 5, d = idx & 31;
            size_t g = row_base + (size_t)(kt * 64 + r) * N3_;
            Ks[r][d] = qkv[g + kcol + d];
            Vs[r][d] = qkv[g + vcol + d];
        }
        __syncthreads();

        // S = Q K^T
        float s[4][4];
        #pragma unroll
        for (int i = 0; i < 4; i++)
            #pragma unroll
            for (int j = 0; j < 4; j++) s[i][j] = 0.f;

        #pragma unroll
        for (int d = 0; d < 32; d++) {
            float a[4], bb[4];
            #pragma unroll
            for (int i = 0; i < 4; i++) a[i]  = Qs[ty * 4 + i][d];
            #pragma unroll
            for (int j = 0; j < 4; j++) bb[j] = Ks[tx * 4 + j][d];
            #pragma unroll
            for (int i = 0; i < 4; i++)
                #pragma unroll
                for (int j = 0; j < 4; j++)
                    s[i][j] = fmaf(a[i], bb[j], s[i][j]);
        }

        // scale + causal mask (mask only on diagonal tile)
        if (kt == qtile) {
            #pragma unroll
            for (int i = 0; i < 4; i++) {
                int qr = ty * 4 + i;
                #pragma unroll
                for (int j = 0; j < 4; j++) {
                    int kc = tx * 4 + j;
                    s[i][j] = (kc <= qr) ? s[i][j] * scale : -1e30f;
                }
            }
        } else {
            #pragma unroll
            for (int i = 0; i < 4; i++)
                #pragma unroll
                for (int j = 0; j < 4; j++) s[i][j] *= scale;
        }

        // Online softmax, per-row (16-lane shuffle groups within a warp)
        #pragma unroll
        for (int i = 0; i < 4; i++) {
            float mx = fmaxf(fmaxf(s[i][0], s[i][1]), fmaxf(s[i][2], s[i][3]));
            #pragma unroll
            for (int off = 8; off >= 1; off >>= 1)
                mx = fmaxf(mx, __shfl_xor_sync(0xffffffffu, mx, off));
            float mnew  = fmaxf(m_i[i], mx);
            float alpha = __expf(m_i[i] - mnew);
            float ps = 0.f;
            #pragma unroll
            for (int j = 0; j < 4; j++) {
                float p = __expf(s[i][j] - mnew);
                Ps[ty * 4 + i][tx * 4 + j] = p;
                ps += p;
            }
            #pragma unroll
            for (int off = 8; off >= 1; off >>= 1)
                ps += __shfl_xor_sync(0xffffffffu, ps, off);
            m_i[i] = mnew;
            l_i[i] = l_i[i] * alpha + ps;
            o[i][0] *= alpha;
            o[i][1] *= alpha;
        }
        __syncwarp();   // Ps rows for this ty-group are produced/consumed in-warp

        // O += P V   (each thread: 4 rows x dims {2tx, 2tx+1})
        #pragma unroll 4
        for (int c = 0; c < 64; c++) {
            float2 v = *reinterpret_cast<const float2*>(&Vs[c][tx * 2]);
            #pragma unroll
            for (int i = 0; i < 4; i++) {
                float p = Ps[ty * 4 + i][c];
                o[i][0] = fmaf(p, v.x, o[i][0]);
                o[i][1] = fmaf(p, v.y, o[i][1]);
            }
        }
    }

    // Normalize and write (bthd layout)
    #pragma unroll
    for (int i = 0; i < 4; i++) {
        int qr = qtile * 64 + ty * 4 + i;
        float inv = 1.0f / l_i[i];
        size_t oidx = ((size_t)(b * T_ + qr)) * E_ + h * DH_ + tx * 2;
        att[oidx]     = o[i][0] * inv;
        att[oidx + 1] = o[i][1] * inv;
    }
}

// ---------------------------------------------------------------------------
// Launch
// ---------------------------------------------------------------------------
extern "C" void kernel_launch(void* const* d_in, const int* in_sizes, int n_in,
                              void* d_out, int out_size)
{
    const float* x    = (const float*)d_in[0];   // [8,2048,256]
    const float* Wqkv = (const float*)d_in[1];   // [256,768]
    const float* bqkv = (const float*)d_in[2];   // [768]
    const float* Wout = (const float*)d_in[3];   // [256,256]
    const float* bout = (const float*)d_in[4];   // [256]
    float* out = (float*)d_out;                  // [8,2048,256]
    (void)in_sizes; (void)n_in; (void)out_size;

    float* qkv = nullptr;
    float* att = nullptr;
    cudaGetSymbolAddress((void**)&qkv, g_qkv);
    cudaGetSymbolAddress((void**)&att, g_att);

    // 1) QKV projection + bias
    {
        dim3 grid(N3_ / 64, M_ / 64);   // (12, 256)
        sgemm_bias_kernel<<<grid, 256>>>(x, Wqkv, bqkv, qkv, M_, N3_, E_);
    }

    // 2) RoPE on q,k
    {
        int total = M_ * 2 * H_ * (DH_ / 2);
        rope_kernel<<<(total + 255) / 256, 256>>>(qkv);
    }

    // 3) Causal flash attention
    {
        dim3 grid(T_ / 64, B_ * H_);    // (32, 64)
        flash_attn_kernel<<<grid, 256>>>(qkv, att);
    }

    // 4) Output projection + bias
    {
        dim3 grid(E_ / 64, M_ / 64);    // (4, 256)
        sgemm_bias_kernel<<<grid, 256>>>(att, Wout, bout, out, M_, E_, E_);
    }
}

// round 13
// speedup vs baseline: 1.0077x; 1.0077x over previous
#include <cuda_runtime.h>
#include <math.h>

#define B_   8
#define T_   2048
#define E_   256
#define H_   8
#define DH_  32
#define M_   (B_ * T_)    // 16384 rows
#define N3_  (3 * E_)     // 768

// Scratch (allocation-free rule: __device__ globals)
__device__ float g_qkv[(size_t)M_ * N3_];   // [16384, 768]  q|k|v per row
__device__ float g_att[(size_t)M_ * E_];    // [16384, 256]  attention output (b,t,h,d)

// ---------------------------------------------------------------------------
// GEMM + bias: C[M,N] = A[M,K] @ W[K,N] + bias[N]
// Tile 64x64, BK=16, 256 threads, 4x4 microtile per thread.
// M,N,K all multiples of 64/16 for this problem -> no bounds checks.
// ---------------------------------------------------------------------------
__global__ void __launch_bounds__(256) sgemm_bias_kernel(
    const float* __restrict__ A, const float* __restrict__ W,
    const float* __restrict__ bias, float* __restrict__ C,
    int M, int N, int K)
{
    __shared__ float As[16][68];   // [k][m]
    __shared__ float Bs[16][68];   // [k][n]

    const int bm = blockIdx.y * 64;
    const int bn = blockIdx.x * 64;
    const int tid = threadIdx.x;
    const int tx = tid & 15;       // column group
    const int ty = tid >> 4;       // row group

    float acc[4][4] = {};

    for (int k0 = 0; k0 < K; k0 += 16) {
        #pragma unroll
        for (int i = 0; i < 4; i++) {
            int idx = tid + i * 256;
            int r = idx >> 4, c = idx & 15;          // 64 rows x 16 cols
            As[c][r] = A[(size_t)(bm + r) * K + (k0 + c)];
        }
        #pragma unroll
        for (int i = 0; i < 4; i++) {
            int idx = tid + i * 256;
            int r = idx >> 6, c = idx & 63;          // 16 rows x 64 cols
            Bs[r][c] = W[(size_t)(k0 + r) * N + (bn + c)];
        }
        __syncthreads();

        #pragma unroll
        for (int kk = 0; kk < 16; kk++) {
            float a[4], bv[4];
            #pragma unroll
            for (int i = 0; i < 4; i++) a[i]  = As[kk][ty * 4 + i];
            #pragma unroll
            for (int j = 0; j < 4; j++) bv[j] = Bs[kk][tx * 4 + j];
            #pragma unroll
            for (int i = 0; i < 4; i++)
                #pragma unroll
                for (int j = 0; j < 4; j++)
                    acc[i][j] = fmaf(a[i], bv[j], acc[i][j]);
        }
        __syncthreads();
    }

    #pragma unroll
    for (int i = 0; i < 4; i++) {
        int row = bm + ty * 4 + i;
        int col = bn + tx * 4;
        float4 r;
        r.x = acc[i][0] + bias[col + 0];
        r.y = acc[i][1] + bias[col + 1];
        r.z = acc[i][2] + bias[col + 2];
        r.w = acc[i][3] + bias[col + 3];
        *reinterpret_cast<float4*>(&C[(size_t)row * N + col]) = r;
    }
}

// ---------------------------------------------------------------------------
// RoPE in-place on q (cols [0,256)) and k (cols [256,512)) of g_qkv.
// One thread per (row, q/k, head, pair). freq_i = 10000^(-i/16), i in [0,16).
// angles up to 2047 rad -> use accurate sincosf (range reduction).
// ---------------------------------------------------------------------------
__global__ void __launch_bounds__(256) rope_kernel(float* __restrict__ qkv)
{
    const int total = M_ * 2 * H_ * (DH_ / 2);   // 4,194,304
    int idx = blockIdx.x * blockDim.x + threadIdx.x;
    if (idx >= total) return;

    int i = idx & 15;            // pair index
    int h = (idx >> 4) & 7;      // head
    int s = (idx >> 7) & 1;      // 0 = q, 1 = k
    int n = idx >> 8;            // row (b*T + t)
    int t = n & (T_ - 1);        // sequence position

    // 10000^(-i/16) = 2^(-i/16 * log2(10000))
    float freq = exp2f(-(float)i * (13.287712379549449f / 16.0f));
    float ang = (float)t * freq;
    float sn, cs;
    sincosf(ang, &sn, &cs);

    size_t base = (size_t)n * N3_ + s * E_ + h * DH_ + 2 * i;
    float x0 = qkv[base];
    float x1 = qkv[base + 1];
    qkv[base]     = x0 * cs - x1 * sn;
    qkv[base + 1] = x1 * cs + x0 * sn;
}

// ---------------------------------------------------------------------------
// Causal flash attention, fp32, Dh=32.
// Grid: (T/64, B*H). 256 threads: tx=tid&15 (cols), ty=tid>>4 (rows).
// Each thread: 4x4 of the 64x64 score tile; O fragment = 4 rows x 2 dims.
// Row softmax groups (fixed ty, 16 lanes) are contiguous within a warp ->
// shuffle reductions + __syncwarp between P-store and PV.
// Output layout: att[(b*T+t)*256 + h*32 + d]  (== bthd reshape).
// ---------------------------------------------------------------------------
__global__ void __launch_bounds__(256) flash_attn_kernel(
    const float* __restrict__ qkv, float* __restrict__ att)
{
    const int qtile = blockIdx.x;         // 0..31
    const int bh    = blockIdx.y;         // 0..63
    const int b = bh >> 3, h = bh & 7;
    const int tid = threadIdx.x;
    const int tx = tid & 15, ty = tid >> 4;

    __shared__ float Qs[64][32];
    __shared__ float Ks[64][33];
    __shared__ float Vs[64][32];
    __shared__ float Ps[64][68];

    const size_t row_base = (size_t)(b * T_) * N3_;
    const int qcol = h * DH_;
    const int kcol = E_ + h * DH_;
    const int vcol = 2 * E_ + h * DH_;

    // Load Q tile (coalesced: 32 floats per row = one 128B line)
    #pragma unroll
    for (int i = 0; i < 8; i++) {
        int idx = tid + i * 256;
        int r = idx >> 5, d = idx & 31;
        Qs[r][d] = qkv[row_base + (size_t)(qtile * 64 + r) * N3_ + qcol + d];
    }

    float m_i[4], l_i[4], o[4][2];
    #pragma unroll
    for (int i = 0; i < 4; i++) {
        m_i[i] = -1e30f; l_i[i] = 0.f; o[i][0] = 0.f; o[i][1] = 0.f;
    }

    const float scale = 0.17677669529663687f;  // 1/sqrt(32)

    for (int kt = 0; kt <= qtile; kt++) {
        __syncthreads();   // Vs/Ks free to overwrite (also covers Q-load on iter 0)
        #pragma unroll
        for (int i = 0; i < 8; i++) {
            int idx = tid + i * 256;
            int r = idx >> 5, d = idx & 31;
            size_t g = row_base + (size_t)(kt * 64 + r) * N3_;
            Ks[r][d] = qkv[g + kcol + d];
            Vs[r][d] = qkv[g + vcol + d];
        }
        __syncthreads();

        // S = Q K^T
        float s[4][4];
        #pragma unroll
        for (int i = 0; i < 4; i++)
            #pragma unroll
            for (int j = 0; j < 4; j++) s[i][j] = 0.f;

        #pragma unroll
        for (int d = 0; d < 32; d++) {
            float a[4], bb[4];
            #pragma unroll
            for (int i = 0; i < 4; i++) a[i]  = Qs[ty * 4 + i][d];
            #pragma unroll
            for (int j = 0; j < 4; j++) bb[j] = Ks[tx * 4 + j][d];
            #pragma unroll
            for (int i = 0; i < 4; i++)
                #pragma unroll
                for (int j = 0; j < 4; j++)
                    s[i][j] = fmaf(a[i], bb[j], s[i][j]);
        }

        // scale + causal mask (mask only on diagonal tile)
        if (kt == qtile) {
            #pragma unroll
            for (int i = 0; i < 4; i++) {
                int qr = ty * 4 + i;
                #pragma unroll
                for (int j = 0; j < 4; j++) {
                    int kc = tx * 4 + j;
                    s[i][j] = (kc <= qr) ? s[i][j] * scale : -1e30f;
                }
            }
        } else {
            #pragma unroll
            for (int i = 0; i < 4; i++)
                #pragma unroll
                for (int j = 0; j < 4; j++) s[i][j] *= scale;
        }

        // Online softmax, per-row (16-lane shuffle groups within a warp)
        #pragma unroll
        for (int i = 0; i < 4; i++) {
            float mx = fmaxf(fmaxf(s[i][0], s[i][1]), fmaxf(s[i][2], s[i][3]));
            #pragma unroll
            for (int off = 8; off >= 1; off >>= 1)
                mx = fmaxf(mx, __shfl_xor_sync(0xffffffffu, mx, off));
            float mnew  = fmaxf(m_i[i], mx);
            float alpha = __expf(m_i[i] - mnew);
            float ps = 0.f;
            #pragma unroll
            for (int j = 0; j < 4; j++) {
                float p = __expf(s[i][j] - mnew);
                Ps[ty * 4 + i][tx * 4 + j] = p;
                ps += p;
            }
            #pragma unroll
            for (int off = 8; off >= 1; off >>= 1)
                ps += __shfl_xor_sync(0xffffffffu, ps, off);
            m_i[i] = mnew;
            l_i[i] = l_i[i] * alpha + ps;
            o[i][0] *= alpha;
            o[i][1] *= alpha;
        }
        __syncwarp();   // Ps rows for this ty-group are produced/consumed in-warp

        // O += P V   (each thread: 4 rows x dims {2tx, 2tx+1})
        #pragma unroll 4
        for (int c = 0; c < 64; c++) {
            float2 v = *reinterpret_cast<const float2*>(&Vs[c][tx * 2]);
            #pragma unroll
            for (int i = 0; i < 4; i++) {
                float p = Ps[ty * 4 + i][c];
                o[i][0] = fmaf(p, v.x, o[i][0]);
                o[i][1] = fmaf(p, v.y, o[i][1]);
            }
        }
    }

    // Normalize and write (bthd layout)
    #pragma unroll
    for (int i = 0; i < 4; i++) {
        int qr = qtile * 64 + ty * 4 + i;
        float inv = 1.0f / l_i[i];
        size_t oidx = ((size_t)(b * T_ + qr)) * E_ + h * DH_ + tx * 2;
        att[oidx]     = o[i][0] * inv;
        att[oidx + 1] = o[i][1] * inv;
    }
}

// ---------------------------------------------------------------------------
// Launch
// ---------------------------------------------------------------------------
extern "C" void kernel_launch(void* const* d_in, const int* in_sizes, int n_in,
                              void* d_out, int out_size)
{
    const float* x    = (const float*)d_in[0];   // [8,2048,256]
    const float* Wqkv = (const float*)d_in[1];   // [256,768]
    const float* bqkv = (const float*)d_in[2];   // [768]
    const float* Wout = (const float*)d_in[3];   // [256,256]
    const float* bout = (const float*)d_in[4];   // [256]
    float* out = (float*)d_out;                  // [8,2048,256]
    (void)in_sizes; (void)n_in; (void)out_size;

    float* qkv = nullptr;
    float* att = nullptr;
    cudaGetSymbolAddress((void**)&qkv, g_qkv);
    cudaGetSymbolAddress((void**)&att, g_att);

    // 1) QKV projection + bias
    {
        dim3 grid(N3_ / 64, M_ / 64);   // (12, 256)
        sgemm_bias_kernel<<<grid, 256>>>(x, Wqkv, bqkv, qkv, M_, N3_, E_);
    }

    // 2) RoPE on q,k
    {
        int total = M_ * 2 * H_ * (DH_ / 2);
        rope_kernel<<<(total + 255) / 256, 256>>>(qkv);
    }

    // 3) Causal flash attention
    {
        dim3 grid(T_ / 64, B_ * H_);    // (32, 64)
        flash_attn_kernel<<<grid, 256>>>(qkv, att);
    }

    // 4) Output projection + bias
    {
        dim3 grid(E_ / 64, M_ / 64);    // (4, 256)
        sgemm_bias_kernel<<<grid, 256>>>(att, Wout, bout, out, M_, E_, E_);
    }
}